// round 12
// baseline (speedup 1.0000x reference)
#include <cuda_runtime.h>
#include <cuda_fp16.h>
#include <cstdint>

#define N_TOK 4096
#define DDIM  1024
#define BK 64                 // halves per k-chunk (4 x k16 planes)
#define STAGE 32768           // A 16KB + B 16KB
#define NSTAGE 3              // 96KB dynamic smem
#define SMEM_TOT (NSTAGE * STAGE)

// Scratch (device globals; no runtime allocation)
__device__ __half g_Xh[(size_t)N_TOK * DDIM];
__device__ __half g_Q[(size_t)N_TOK * DDIM];
__device__ __half g_K[(size_t)N_TOK * DDIM];
__device__ __half g_Vt[(size_t)DDIM * N_TOK];     // V^T [dim][token]
__device__ __half g_Wt[3][(size_t)DDIM * DDIM];   // W^T [out][in]
__device__ __half g_P[(size_t)N_TOK * N_TOK];
__device__ float  g_rsum[N_TOK];

// Smem tile layout (per stage): A = 128 rows x 64 halves (128B/row) at 0, B at 16384.
// 16B chunk c (0..7) of row r stored at r*128 + 16*(c ^ (r & 7)).
// Conflict-free for cp.async 16B stores and ldmatrix.x4 8-lane rounds.

__device__ __forceinline__ void mma_f16(float d[4], uint32_t a0, uint32_t a1, uint32_t a2,
                                        uint32_t a3, uint32_t b0, uint32_t b1) {
    asm volatile(
        "mma.sync.aligned.m16n8k16.row.col.f32.f16.f16.f32 "
        "{%0,%1,%2,%3}, {%4,%5,%6,%7}, {%8,%9}, {%0,%1,%2,%3};\n"
        : "+f"(d[0]), "+f"(d[1]), "+f"(d[2]), "+f"(d[3])
        : "r"(a0), "r"(a1), "r"(a2), "r"(a3), "r"(b0), "r"(b1));
}
__device__ __forceinline__ void cp_async16(uint32_t s, const void* g) {
    asm volatile("cp.async.cg.shared.global [%0], [%1], 16;" :: "r"(s), "l"(g));
}
__device__ __forceinline__ void cp_commit() {
    asm volatile("cp.async.commit_group;" ::: "memory");
}
template <int N>
__device__ __forceinline__ void cp_wait() {
    asm volatile("cp.async.wait_group %0;" :: "n"(N) : "memory");
}
__device__ __forceinline__ void ldsm_x4(uint32_t* r, uint32_t addr) {
    asm volatile("ldmatrix.sync.aligned.m8n8.x4.shared.b16 {%0,%1,%2,%3}, [%4];"
        : "=r"(r[0]), "=r"(r[1]), "=r"(r[2]), "=r"(r[3]) : "r"(addr));
}

// Issue cp.async for one stage: 8 x 16B chunks each of A and B per thread (128 thr).
__device__ __forceinline__ void stage_load(
    uint32_t sbase, const __half* __restrict__ A, const __half* __restrict__ B,
    int lda, int ldb, int bm, int bn, int kt, int tid)
{
#pragma unroll
    for (int i = 0; i < 8; i++) {
        int chunk = tid + i * 128;
        int row = chunk >> 3, c = chunk & 7;
        uint32_t so = row * 128 + 16 * (c ^ (row & 7));
        cp_async16(sbase + so,         A + (size_t)(bm + row) * lda + kt * BK + c * 8);
        cp_async16(sbase + 16384 + so, B + (size_t)(bn + row) * ldb + kt * BK + c * 8);
    }
}

// CTA 128x128, 4 warps as 2(M) x 2(N), warp tile 64x64, 3-stage cp.async + ldmatrix,
// fragment-level double buffering (LDSM for h+1 overlaps MMA of h).
// A [M x K] half row-major, B [N x K] half row-major, fp32 accum.
__device__ __forceinline__ void gemm_main(
    const __half* __restrict__ A, const __half* __restrict__ B,
    int lda, int ldb, int kIters, int bm, int bn,
    char* smem, float (&acc)[4][8][4])
{
    const int tid = threadIdx.x;
    const uint32_t sb = (uint32_t)__cvta_generic_to_shared(smem);

#pragma unroll
    for (int mi = 0; mi < 4; mi++)
#pragma unroll
        for (int ni = 0; ni < 8; ni++)
#pragma unroll
            for (int j = 0; j < 4; j++) acc[mi][ni][j] = 0.f;

    stage_load(sb,         A, B, lda, ldb, bm, bn, 0, tid);
    cp_commit();
    stage_load(sb + STAGE, A, B, lda, ldb, bm, bn, 1, tid);
    cp_commit();

    const int lane = tid & 31, w = tid >> 5;
    const int wm = (w & 1) * 64, wn = (w >> 1) * 64;
    const int rA = wm + (lane & 15), rB = wn + (lane & 15);
    const int cl = lane >> 4;
    uint32_t aAddr[4], bAddr[4];
#pragma unroll
    for (int h = 0; h < 4; h++) {
        aAddr[h] = rA * 128 + 16 * ((2 * h + cl) ^ (rA & 7));
        bAddr[h] = 16384 + rB * 128 + 16 * ((2 * h + cl) ^ (rB & 7));
    }

    uint32_t a[2][4][4], bq[2][4][4];

    for (int kt = 0; kt < kIters; ++kt) {
        cp_wait<1>();
        __syncthreads();
        const uint32_t sst = sb + (uint32_t)((kt % NSTAGE) * STAGE);

        // Prefetch stage kt+2 BEFORE compute (stage (kt+2)%3 proven consumed by sync).
        if (kt + 2 < kIters)
            stage_load(sb + (uint32_t)(((kt + 2) % NSTAGE) * STAGE),
                       A, B, lda, ldb, bm, bn, kt + 2, tid);
        cp_commit();   // unconditional: keeps wait_group accounting aligned in the tail

        // Load h=0 fragments
#pragma unroll
        for (int mi = 0; mi < 4; mi++) ldsm_x4(a[0][mi],  sst + aAddr[0] + mi * 2048);
#pragma unroll
        for (int nb = 0; nb < 4; nb++) ldsm_x4(bq[0][nb], sst + bAddr[0] + nb * 2048);

#pragma unroll
        for (int h = 0; h < 4; h++) {
            const int cur = h & 1, nxt = cur ^ 1;
            // Prefetch fragments for h+1 before the MMA body of h
            if (h < 3) {
#pragma unroll
                for (int mi = 0; mi < 4; mi++)
                    ldsm_x4(a[nxt][mi],  sst + aAddr[h + 1] + mi * 2048);
#pragma unroll
                for (int nb = 0; nb < 4; nb++)
                    ldsm_x4(bq[nxt][nb], sst + bAddr[h + 1] + nb * 2048);
            }
#pragma unroll
            for (int mi = 0; mi < 4; mi++)
#pragma unroll
                for (int ni = 0; ni < 8; ni++) {
                    const int nb = ni >> 1;
                    const uint32_t b0 = (ni & 1) ? bq[cur][nb][1] : bq[cur][nb][0];
                    const uint32_t b1 = (ni & 1) ? bq[cur][nb][3] : bq[cur][nb][2];
                    mma_f16(acc[mi][ni], a[cur][mi][0], a[cur][mi][1],
                            a[cur][mi][2], a[cur][mi][3], b0, b1);
                }
        }
    }
}

// ---------- prep: x->half, W transposes, rsum zero (one launch) ----------
// blocks [0, 2048): convert x. blocks [2048, 5120): transpose Wq/Wk/Wv.
__global__ void __launch_bounds__(256)
prep_kernel(const float* __restrict__ x, const float* __restrict__ wq,
            const float* __restrict__ wk, const float* __restrict__ wv)
{
    __shared__ float t[32][33];
    const int b = blockIdx.x;
    if (b < 2048) {
        if (b < 16) g_rsum[b * 256 + threadIdx.x] = 0.f;
        const size_t base = ((size_t)b * 256 + threadIdx.x) * 8;
        float4 v0 = *reinterpret_cast<const float4*>(x + base);
        float4 v1 = *reinterpret_cast<const float4*>(x + base + 4);
        __half2* o = reinterpret_cast<__half2*>(g_Xh + base);
        o[0] = __floats2half2_rn(v0.x, v0.y);
        o[1] = __floats2half2_rn(v0.z, v0.w);
        o[2] = __floats2half2_rn(v1.x, v1.y);
        o[3] = __floats2half2_rn(v1.z, v1.w);
    } else {
        const int i = b - 2048;
        const int z = i >> 10, rem = i & 1023;
        const float* in = (z == 0) ? wq : (z == 1) ? wk : wv;
        __half* dst = g_Wt[z];
        const int bx = (rem & 31) * 32, by = (rem >> 5) * 32;
        const int tx = threadIdx.x & 31, ty = threadIdx.x >> 5;
#pragma unroll
        for (int i2 = 0; i2 < 32; i2 += 8)
            t[ty + i2][tx] = in[(size_t)(by + ty + i2) * DDIM + bx + tx];
        __syncthreads();
#pragma unroll
        for (int i2 = 0; i2 < 32; i2 += 8)
            dst[(size_t)(bx + ty + i2) * DDIM + by + tx] = __float2half(t[tx][ty + i2]);
    }
}

// ---------- Kernel 1: Q/K = X @ W + b ; z=2 computes Vt = Wv^T X^T + bv directly ----------
__global__ void __launch_bounds__(128, 2)
qkv_kernel(const float* __restrict__ bq, const float* __restrict__ bk,
           const float* __restrict__ bv)
{
    extern __shared__ __align__(16) char smem[];
    const int z = blockIdx.z;
    const __half* A; const __half* B; const float* bias; __half* O;
    int bm, bn, ldc;
    if (z < 2) {
        A = g_Xh; B = g_Wt[z]; O = (z == 0) ? g_Q : g_K;
        bias = (z == 0) ? bq : bk;
        bm = blockIdx.y * 128; bn = blockIdx.x * 128; ldc = DDIM;
    } else {
        // Vt[d][t] = sum_k Wt[2][d][k] * Xh[t][k] + bv[d]
        A = g_Wt[2]; B = g_Xh; O = g_Vt; bias = bv;
        bm = blockIdx.x * 128; bn = blockIdx.y * 128; ldc = N_TOK;
    }

    float acc[4][8][4];
    gemm_main(A, B, DDIM, DDIM, DDIM / BK, bm, bn, smem, acc);

    const int w = threadIdx.x >> 5, lane = threadIdx.x & 31;
    const int wm = (w & 1) * 64, wn = (w >> 1) * 64;
    const int gid = lane >> 2, tig = lane & 3;
#pragma unroll
    for (int mi = 0; mi < 4; mi++) {
        int r0 = bm + wm + mi * 16 + gid;
#pragma unroll
        for (int ni = 0; ni < 8; ni++) {
            int c = bn + wn + ni * 8 + 2 * tig;
            float b0, b1, b2, b3;
            if (z < 2) { b0 = bias[c]; b1 = bias[c + 1]; b2 = b0; b3 = b1; }
            else       { b0 = b1 = bias[r0]; b2 = b3 = bias[r0 + 8]; }
            *reinterpret_cast<__half2*>(&O[(size_t)r0 * ldc + c]) =
                __floats2half2_rn(acc[mi][ni][0] + b0, acc[mi][ni][1] + b1);
            *reinterpret_cast<__half2*>(&O[(size_t)(r0 + 8) * ldc + c]) =
                __floats2half2_rn(acc[mi][ni][2] + b2, acc[mi][ni][3] + b3);
        }
    }
}

// ---------- Kernel 2: P = exp(tanh(Q @ K^T)/32), fused row-sum atomics ----------
__global__ void __launch_bounds__(128, 2)
score_kernel()
{
    extern __shared__ __align__(16) char smem[];
    const int bm = blockIdx.y * 128, bn = blockIdx.x * 128;
    float acc[4][8][4];
    gemm_main(g_Q, g_K, DDIM, DDIM, DDIM / BK, bm, bn, smem, acc);

    const int w = threadIdx.x >> 5, lane = threadIdx.x & 31;
    const int wm = (w & 1) * 64, wn = (w >> 1) * 64;
    const int gid = lane >> 2, tig = lane & 3;
    const float sc = 0.03125f;  // 1/sqrt(1024)
#pragma unroll
    for (int mi = 0; mi < 4; mi++) {
        int r0 = bm + wm + mi * 16 + gid;
        float slo = 0.f, shi = 0.f;
#pragma unroll
        for (int ni = 0; ni < 8; ni++) {
            int c = bn + wn + ni * 8 + 2 * tig;
            float e[4];
#pragma unroll
            for (int q = 0; q < 4; q++) {
                float t;
                asm("tanh.approx.f32 %0, %1;" : "=f"(t) : "f"(acc[mi][ni][q]));
                e[q] = __expf(t * sc);
            }
            slo += e[0] + e[1];
            shi += e[2] + e[3];
            *reinterpret_cast<__half2*>(&g_P[(size_t)r0 * N_TOK + c]) =
                __floats2half2_rn(e[0], e[1]);
            *reinterpret_cast<__half2*>(&g_P[(size_t)(r0 + 8) * N_TOK + c]) =
                __floats2half2_rn(e[2], e[3]);
        }
        slo += __shfl_xor_sync(0xffffffffu, slo, 1);
        slo += __shfl_xor_sync(0xffffffffu, slo, 2);
        shi += __shfl_xor_sync(0xffffffffu, shi, 1);
        shi += __shfl_xor_sync(0xffffffffu, shi, 2);
        if (tig == 0) {
            atomicAdd(&g_rsum[r0], slo);
            atomicAdd(&g_rsum[r0 + 8], shi);
        }
    }
}

// ---------- Kernel 3: out = (P @ V) / rsum (fp32 out) ----------
__global__ void __launch_bounds__(128, 2)
pv_kernel(float* __restrict__ out)
{
    extern __shared__ __align__(16) char smem[];
    const int bm = blockIdx.y * 128, bn = blockIdx.x * 128;
    float acc[4][8][4];
    gemm_main(g_P, g_Vt, N_TOK, N_TOK, N_TOK / BK, bm, bn, smem, acc);

    const int w = threadIdx.x >> 5, lane = threadIdx.x & 31;
    const int wm = (w & 1) * 64, wn = (w >> 1) * 64;
    const int gid = lane >> 2, tig = lane & 3;
#pragma unroll
    for (int mi = 0; mi < 4; mi++) {
        int r0 = bm + wm + mi * 16 + gid;
        float inv0 = 1.0f / g_rsum[r0];
        float inv1 = 1.0f / g_rsum[r0 + 8];
#pragma unroll
        for (int ni = 0; ni < 8; ni++) {
            int c = bn + wn + ni * 8 + 2 * tig;
            float2 v0 = make_float2(acc[mi][ni][0] * inv0, acc[mi][ni][1] * inv0);
            float2 v1 = make_float2(acc[mi][ni][2] * inv1, acc[mi][ni][3] * inv1);
            *reinterpret_cast<float2*>(&out[(size_t)r0 * DDIM + c]) = v0;
            *reinterpret_cast<float2*>(&out[(size_t)(r0 + 8) * DDIM + c]) = v1;
        }
    }
}

extern "C" void kernel_launch(void* const* d_in, const int* in_sizes, int n_in,
                              void* d_out, int out_size)
{
    const float* x  = (const float*)d_in[0];
    const float* Wq = (const float*)d_in[1];
    const float* bq = (const float*)d_in[2];
    const float* Wk = (const float*)d_in[3];
    const float* bk = (const float*)d_in[4];
    const float* Wv = (const float*)d_in[5];
    const float* bv = (const float*)d_in[6];
    float* out = (float*)d_out;

    cudaFuncSetAttribute(qkv_kernel,   cudaFuncAttributeMaxDynamicSharedMemorySize, SMEM_TOT);
    cudaFuncSetAttribute(score_kernel, cudaFuncAttributeMaxDynamicSharedMemorySize, SMEM_TOT);
    cudaFuncSetAttribute(pv_kernel,    cudaFuncAttributeMaxDynamicSharedMemorySize, SMEM_TOT);

    prep_kernel<<<5120, 256>>>(x, Wq, Wk, Wv);
    qkv_kernel<<<dim3(DDIM / 128, N_TOK / 128, 3), 128, SMEM_TOT>>>(bq, bk, bv);
    score_kernel<<<dim3(N_TOK / 128, N_TOK / 128), 128, SMEM_TOT>>>();
    pv_kernel<<<dim3(DDIM / 128, N_TOK / 128), 128, SMEM_TOT>>>(out);
}

// round 13
// speedup vs baseline: 1.0350x; 1.0350x over previous
#include <cuda_runtime.h>
#include <cuda_fp16.h>
#include <cstdint>

#define N_TOK 4096
#define DDIM  1024
#define BK 64                 // halves per k-chunk (4 x k16 planes)
#define STAGE 32768           // A 16KB + B 16KB
#define NSTAGE 3              // 96KB dynamic smem
#define SMEM_TOT (NSTAGE * STAGE)

// Scratch (device globals; no runtime allocation)
__device__ __half g_Xh[(size_t)N_TOK * DDIM];
__device__ __half g_Q[(size_t)N_TOK * DDIM];
__device__ __half g_K[(size_t)N_TOK * DDIM];
__device__ __half g_Vt[(size_t)DDIM * N_TOK];     // V^T [dim][token]
__device__ __half g_Wt[3][(size_t)DDIM * DDIM];   // W^T [out][in]
__device__ __half g_P[(size_t)N_TOK * N_TOK];
__device__ float  g_rsum[N_TOK];

// Smem tile layout (per stage): A = 128 rows x 64 halves (128B/row) at 0, B at 16384.
// 16B chunk c (0..7) of row r stored at r*128 + 16*(c ^ (r & 7)).
// Conflict-free for cp.async 16B stores and ldmatrix.x4 8-lane rounds.

__device__ __forceinline__ void mma_f16(float d[4], uint32_t a0, uint32_t a1, uint32_t a2,
                                        uint32_t a3, uint32_t b0, uint32_t b1) {
    asm volatile(
        "mma.sync.aligned.m16n8k16.row.col.f32.f16.f16.f32 "
        "{%0,%1,%2,%3}, {%4,%5,%6,%7}, {%8,%9}, {%0,%1,%2,%3};\n"
        : "+f"(d[0]), "+f"(d[1]), "+f"(d[2]), "+f"(d[3])
        : "r"(a0), "r"(a1), "r"(a2), "r"(a3), "r"(b0), "r"(b1));
}
__device__ __forceinline__ void cp_async16(uint32_t s, const void* g) {
    asm volatile("cp.async.cg.shared.global [%0], [%1], 16;" :: "r"(s), "l"(g));
}
__device__ __forceinline__ void cp_commit() {
    asm volatile("cp.async.commit_group;" ::: "memory");
}
template <int N>
__device__ __forceinline__ void cp_wait() {
    asm volatile("cp.async.wait_group %0;" :: "n"(N) : "memory");
}
__device__ __forceinline__ void ldsm_x4(uint32_t* r, uint32_t addr) {
    asm volatile("ldmatrix.sync.aligned.m8n8.x4.shared.b16 {%0,%1,%2,%3}, [%4];"
        : "=r"(r[0]), "=r"(r[1]), "=r"(r[2]), "=r"(r[3]) : "r"(addr));
}

// Issue cp.async for one stage: 4 x 16B chunks each of A and B per thread (256 thr).
__device__ __forceinline__ void stage_load(
    uint32_t sbase, const __half* __restrict__ A, const __half* __restrict__ B,
    int lda, int ldb, int bm, int bn, int kt, int tid)
{
#pragma unroll
    for (int i = 0; i < 4; i++) {
        int chunk = tid + i * 256;
        int row = chunk >> 3, c = chunk & 7;
        uint32_t so = row * 128 + 16 * (c ^ (row & 7));
        cp_async16(sbase + so,         A + (size_t)(bm + row) * lda + kt * BK + c * 8);
        cp_async16(sbase + 16384 + so, B + (size_t)(bn + row) * ldb + kt * BK + c * 8);
    }
}

// CTA 128x128, 8 warps as 4(M) x 2(N), warp tile 32x64, 3-stage cp.async + ldmatrix.
// 2 CTAs/SM -> 4 warps/SMSP for latency hiding.
// A [M x K] half row-major, B [N x K] half row-major, fp32 accum.
__device__ __forceinline__ void gemm_main(
    const __half* __restrict__ A, const __half* __restrict__ B,
    int lda, int ldb, int kIters, int bm, int bn,
    char* smem, float (&acc)[2][8][4])
{
    const int tid = threadIdx.x;
    const uint32_t sb = (uint32_t)__cvta_generic_to_shared(smem);

#pragma unroll
    for (int mi = 0; mi < 2; mi++)
#pragma unroll
        for (int ni = 0; ni < 8; ni++)
#pragma unroll
            for (int j = 0; j < 4; j++) acc[mi][ni][j] = 0.f;

    stage_load(sb,         A, B, lda, ldb, bm, bn, 0, tid);
    cp_commit();
    stage_load(sb + STAGE, A, B, lda, ldb, bm, bn, 1, tid);
    cp_commit();

    const int lane = tid & 31, w = tid >> 5;
    const int wm = (w & 3) * 32, wn = (w >> 2) * 64;
    const int rA = wm + (lane & 15), rB = wn + (lane & 15);
    const int cl = lane >> 4;
    uint32_t aAddr[4], bAddr[4];
#pragma unroll
    for (int h = 0; h < 4; h++) {
        aAddr[h] = rA * 128 + 16 * ((2 * h + cl) ^ (rA & 7));
        bAddr[h] = 16384 + rB * 128 + 16 * ((2 * h + cl) ^ (rB & 7));
    }

    for (int kt = 0; kt < kIters; ++kt) {
        cp_wait<1>();
        __syncthreads();
        const uint32_t sst = sb + (uint32_t)((kt % NSTAGE) * STAGE);

        // Prefetch stage kt+2 BEFORE compute (stage (kt+2)%3 proven consumed by sync).
        if (kt + 2 < kIters)
            stage_load(sb + (uint32_t)(((kt + 2) % NSTAGE) * STAGE),
                       A, B, lda, ldb, bm, bn, kt + 2, tid);
        cp_commit();   // unconditional: keeps wait_group accounting aligned in the tail

#pragma unroll
        for (int h = 0; h < 4; h++) {
            uint32_t a[2][4], bq[4][4];
#pragma unroll
            for (int mi = 0; mi < 2; mi++)
                ldsm_x4(a[mi], sst + aAddr[h] + mi * 2048);
#pragma unroll
            for (int nb = 0; nb < 4; nb++)
                ldsm_x4(bq[nb], sst + bAddr[h] + nb * 2048);
#pragma unroll
            for (int mi = 0; mi < 2; mi++)
#pragma unroll
                for (int ni = 0; ni < 8; ni++) {
                    const int nb = ni >> 1;
                    const uint32_t b0 = (ni & 1) ? bq[nb][1] : bq[nb][0];
                    const uint32_t b1 = (ni & 1) ? bq[nb][3] : bq[nb][2];
                    mma_f16(acc[mi][ni], a[mi][0], a[mi][1], a[mi][2], a[mi][3], b0, b1);
                }
        }
    }
}

// ---------- prep: x->half, W transposes, rsum zero (one launch) ----------
// blocks [0, 2048): convert x. blocks [2048, 5120): transpose Wq/Wk/Wv.
__global__ void __launch_bounds__(256)
prep_kernel(const float* __restrict__ x, const float* __restrict__ wq,
            const float* __restrict__ wk, const float* __restrict__ wv)
{
    __shared__ float t[32][33];
    const int b = blockIdx.x;
    if (b < 2048) {
        if (b < 16) g_rsum[b * 256 + threadIdx.x] = 0.f;
        const size_t base = ((size_t)b * 256 + threadIdx.x) * 8;
        float4 v0 = *reinterpret_cast<const float4*>(x + base);
        float4 v1 = *reinterpret_cast<const float4*>(x + base + 4);
        __half2* o = reinterpret_cast<__half2*>(g_Xh + base);
        o[0] = __floats2half2_rn(v0.x, v0.y);
        o[1] = __floats2half2_rn(v0.z, v0.w);
        o[2] = __floats2half2_rn(v1.x, v1.y);
        o[3] = __floats2half2_rn(v1.z, v1.w);
    } else {
        const int i = b - 2048;
        const int z = i >> 10, rem = i & 1023;
        const float* in = (z == 0) ? wq : (z == 1) ? wk : wv;
        __half* dst = g_Wt[z];
        const int bx = (rem & 31) * 32, by = (rem >> 5) * 32;
        const int tx = threadIdx.x & 31, ty = threadIdx.x >> 5;
#pragma unroll
        for (int i2 = 0; i2 < 32; i2 += 8)
            t[ty + i2][tx] = in[(size_t)(by + ty + i2) * DDIM + bx + tx];
        __syncthreads();
#pragma unroll
        for (int i2 = 0; i2 < 32; i2 += 8)
            dst[(size_t)(bx + ty + i2) * DDIM + by + tx] = __float2half(t[tx][ty + i2]);
    }
}

// ---------- Kernel 1: Q/K = X @ W + b ; z=2 computes Vt = Wv^T X^T + bv directly ----------
__global__ void __launch_bounds__(256, 2)
qkv_kernel(const float* __restrict__ bq, const float* __restrict__ bk,
           const float* __restrict__ bv)
{
    extern __shared__ __align__(16) char smem[];
    const int z = blockIdx.z;
    const __half* A; const __half* B; const float* bias; __half* O;
    int bm, bn, ldc;
    if (z < 2) {
        A = g_Xh; B = g_Wt[z]; O = (z == 0) ? g_Q : g_K;
        bias = (z == 0) ? bq : bk;
        bm = blockIdx.y * 128; bn = blockIdx.x * 128; ldc = DDIM;
    } else {
        // Vt[d][t] = sum_k Wt[2][d][k] * Xh[t][k] + bv[d]
        A = g_Wt[2]; B = g_Xh; O = g_Vt; bias = bv;
        bm = blockIdx.x * 128; bn = blockIdx.y * 128; ldc = N_TOK;
    }

    float acc[2][8][4];
    gemm_main(A, B, DDIM, DDIM, DDIM / BK, bm, bn, smem, acc);

    const int w = threadIdx.x >> 5, lane = threadIdx.x & 31;
    const int wm = (w & 3) * 32, wn = (w >> 2) * 64;
    const int gid = lane >> 2, tig = lane & 3;
#pragma unroll
    for (int mi = 0; mi < 2; mi++) {
        int r0 = bm + wm + mi * 16 + gid;
#pragma unroll
        for (int ni = 0; ni < 8; ni++) {
            int c = bn + wn + ni * 8 + 2 * tig;
            float b0, b1, b2, b3;
            if (z < 2) { b0 = bias[c]; b1 = bias[c + 1]; b2 = b0; b3 = b1; }
            else       { b0 = b1 = bias[r0]; b2 = b3 = bias[r0 + 8]; }
            *reinterpret_cast<__half2*>(&O[(size_t)r0 * ldc + c]) =
                __floats2half2_rn(acc[mi][ni][0] + b0, acc[mi][ni][1] + b1);
            *reinterpret_cast<__half2*>(&O[(size_t)(r0 + 8) * ldc + c]) =
                __floats2half2_rn(acc[mi][ni][2] + b2, acc[mi][ni][3] + b3);
        }
    }
}

// ---------- Kernel 2: P = exp(tanh(Q @ K^T)/32), fused row-sum atomics ----------
__global__ void __launch_bounds__(256, 2)
score_kernel()
{
    extern __shared__ __align__(16) char smem[];
    const int bm = blockIdx.y * 128, bn = blockIdx.x * 128;
    float acc[2][8][4];
    gemm_main(g_Q, g_K, DDIM, DDIM, DDIM / BK, bm, bn, smem, acc);

    const int w = threadIdx.x >> 5, lane = threadIdx.x & 31;
    const int wm = (w & 3) * 32, wn = (w >> 2) * 64;
    const int gid = lane >> 2, tig = lane & 3;
    const float sc = 0.03125f;  // 1/sqrt(1024)
#pragma unroll
    for (int mi = 0; mi < 2; mi++) {
        int r0 = bm + wm + mi * 16 + gid;
        float slo = 0.f, shi = 0.f;
#pragma unroll
        for (int ni = 0; ni < 8; ni++) {
            int c = bn + wn + ni * 8 + 2 * tig;
            float e[4];
#pragma unroll
            for (int q = 0; q < 4; q++) {
                float t;
                asm("tanh.approx.f32 %0, %1;" : "=f"(t) : "f"(acc[mi][ni][q]));
                e[q] = __expf(t * sc);
            }
            slo += e[0] + e[1];
            shi += e[2] + e[3];
            *reinterpret_cast<__half2*>(&g_P[(size_t)r0 * N_TOK + c]) =
                __floats2half2_rn(e[0], e[1]);
            *reinterpret_cast<__half2*>(&g_P[(size_t)(r0 + 8) * N_TOK + c]) =
                __floats2half2_rn(e[2], e[3]);
        }
        slo += __shfl_xor_sync(0xffffffffu, slo, 1);
        slo += __shfl_xor_sync(0xffffffffu, slo, 2);
        shi += __shfl_xor_sync(0xffffffffu, shi, 1);
        shi += __shfl_xor_sync(0xffffffffu, shi, 2);
        if (tig == 0) {
            atomicAdd(&g_rsum[r0], slo);
            atomicAdd(&g_rsum[r0 + 8], shi);
        }
    }
}

// ---------- Kernel 3: out = (P @ V) / rsum (fp32 out) ----------
__global__ void __launch_bounds__(256, 2)
pv_kernel(float* __restrict__ out)
{
    extern __shared__ __align__(16) char smem[];
    const int bm = blockIdx.y * 128, bn = blockIdx.x * 128;
    float acc[2][8][4];
    gemm_main(g_P, g_Vt, N_TOK, N_TOK, N_TOK / BK, bm, bn, smem, acc);

    const int w = threadIdx.x >> 5, lane = threadIdx.x & 31;
    const int wm = (w & 3) * 32, wn = (w >> 2) * 64;
    const int gid = lane >> 2, tig = lane & 3;
#pragma unroll
    for (int mi = 0; mi < 2; mi++) {
        int r0 = bm + wm + mi * 16 + gid;
        float inv0 = 1.0f / g_rsum[r0];
        float inv1 = 1.0f / g_rsum[r0 + 8];
#pragma unroll
        for (int ni = 0; ni < 8; ni++) {
            int c = bn + wn + ni * 8 + 2 * tig;
            float2 v0 = make_float2(acc[mi][ni][0] * inv0, acc[mi][ni][1] * inv0);
            float2 v1 = make_float2(acc[mi][ni][2] * inv1, acc[mi][ni][3] * inv1);
            *reinterpret_cast<float2*>(&out[(size_t)r0 * DDIM + c]) = v0;
            *reinterpret_cast<float2*>(&out[(size_t)(r0 + 8) * DDIM + c]) = v1;
        }
    }
}

extern "C" void kernel_launch(void* const* d_in, const int* in_sizes, int n_in,
                              void* d_out, int out_size)
{
    const float* x  = (const float*)d_in[0];
    const float* Wq = (const float*)d_in[1];
    const float* bq = (const float*)d_in[2];
    const float* Wk = (const float*)d_in[3];
    const float* bk = (const float*)d_in[4];
    const float* Wv = (const float*)d_in[5];
    const float* bv = (const float*)d_in[6];
    float* out = (float*)d_out;

    cudaFuncSetAttribute(qkv_kernel,   cudaFuncAttributeMaxDynamicSharedMemorySize, SMEM_TOT);
    cudaFuncSetAttribute(score_kernel, cudaFuncAttributeMaxDynamicSharedMemorySize, SMEM_TOT);
    cudaFuncSetAttribute(pv_kernel,    cudaFuncAttributeMaxDynamicSharedMemorySize, SMEM_TOT);

    prep_kernel<<<5120, 256>>>(x, Wq, Wk, Wv);
    qkv_kernel<<<dim3(DDIM / 128, N_TOK / 128, 3), 256, SMEM_TOT>>>(bq, bk, bv);
    score_kernel<<<dim3(N_TOK / 128, N_TOK / 128), 256, SMEM_TOT>>>();
    pv_kernel<<<dim3(DDIM / 128, N_TOK / 128), 256, SMEM_TOT>>>(out);
}